// round 12
// baseline (speedup 1.0000x reference)
#include <cuda_runtime.h>

#define NG 36

__device__ float d_gates[NG * 8];

// Fuse Rz*Ry*Rx per (layer,qubit) in double precision.
__global__ void prep_gates(const float* __restrict__ params) {
    int g = threadIdx.x;
    if (g >= NG) return;
    double tx = (double)params[3*g]   * 0.5;
    double ty = (double)params[3*g+1] * 0.5;
    double tz = (double)params[3*g+2] * 0.5;
    double cx = cos(tx), sx = sin(tx), cy = cos(ty), sy = sin(ty), cz = cos(tz), sz = sin(tz);
    // M = Ry*Rx
    double m00r =  cy*cx, m00i =  sy*sx;
    double m01r = -sy*cx, m01i = -cy*sx;
    double m10r =  sy*cx, m10i = -cy*sx;
    double m11r =  cy*cx, m11i = -sy*sx;
    float* o = d_gates + g * 8;
    // row0 *= (cz - i sz), row1 *= (cz + i sz)
    o[0] = (float)(cz*m00r + sz*m00i); o[1] = (float)(cz*m00i - sz*m00r);
    o[2] = (float)(cz*m01r + sz*m01i); o[3] = (float)(cz*m01i - sz*m01r);
    o[4] = (float)(cz*m10r - sz*m10i); o[5] = (float)(cz*m10i + sz*m10r);
    o[6] = (float)(cz*m11r - sz*m11i); o[7] = (float)(cz*m11i + sz*m11r);
}

// One batch element per CTA. State in smem (split re/im). Wire q <-> bit (11-q).
__global__ void __launch_bounds__(256) qc(const float* __restrict__ x, float* __restrict__ out) {
    __shared__ float sre[4096], sim[4096];
    __shared__ float sg[NG * 8];
    __shared__ float red[8];
    __shared__ float zr[8][12];

    const int t = threadIdx.x, w = t >> 5, l = t & 31;
    const long long base = (long long)blockIdx.x * 4096;

    // NG*8 = 288 > 256 threads — grid-stride the copy.
    for (int e = t; e < NG * 8; e += 256) sg[e] = d_gates[e];

    // ---- load + norm ----
    float v[16]; float s = 0.f;
    const float4* xv = (const float4*)(x + base);
#pragma unroll
    for (int m = 0; m < 4; m++) {
        float4 f = xv[t + m * 256];
        v[4*m] = f.x; v[4*m+1] = f.y; v[4*m+2] = f.z; v[4*m+3] = f.w;
        s += f.x*f.x + f.y*f.y + f.z*f.z + f.w*f.w;
    }
#pragma unroll
    for (int o = 16; o; o >>= 1) s += __shfl_xor_sync(~0u, s, o);
    if (!l) red[w] = s;
    __syncthreads();
    s = red[0] + red[1] + red[2] + red[3] + red[4] + red[5] + red[6] + red[7];
    const float rn = rsqrtf(s);
#pragma unroll
    for (int m = 0; m < 4; m++) {
        int i = (t + m * 256) * 4;
#pragma unroll
        for (int k = 0; k < 4; k++) { sre[i+k] = v[4*m+k] * rn; sim[i+k] = 0.f; }
    }
    __syncthreads();

    // ---- circuit ----
    for (int layer = 0; layer < 3; layer++) {
        for (int q = 0; q < 12; q++) {
            const float* u = &sg[(layer * 12 + q) * 8];
            const float u00r=u[0], u00i=u[1], u01r=u[2], u01i=u[3];
            const float u10r=u[4], u10i=u[5], u11r=u[6], u11i=u[7];
            const int b = 11 - q, mlo = (1 << b) - 1;
#pragma unroll
            for (int m = 0; m < 8; m++) {
                int p = t + m * 256;
                int i0 = ((p & ~mlo) << 1) | (p & mlo);
                int i1 = i0 | (1 << b);
                float ar = sre[i0], ai = sim[i0], cr = sre[i1], ci = sim[i1];
                sre[i0] = u00r*ar - u00i*ai + u01r*cr - u01i*ci;
                sim[i0] = u00r*ai + u00i*ar + u01r*ci + u01i*cr;
                sre[i1] = u10r*ar - u10i*ai + u11r*cr - u11i*ci;
                sim[i1] = u10r*ai + u10i*ar + u11r*ci + u11i*cr;
            }
            __syncthreads();
        }
        // CNOT ring (q -> q+1 mod 12, q=0..11) as one permutation gather.
        float tr[16], ti[16];
#pragma unroll
        for (int m = 0; m < 16; m++) {
            int i = t + m * 256;
            int lo  = (i ^ (i >> 1)) & 0x3FF;               // b_j = c_j ^ c_{j+1}, j=0..9
            int b10 = ((i >> 10) ^ (i >> 11) ^ i) & 1;      // c10 ^ c11 ^ c0
            int b11 = ((i >> 11) ^ i) & 1;                  // c11 ^ c0
            int src = lo | (b10 << 10) | (b11 << 11);
            tr[m] = sre[src]; ti[m] = sim[src];
        }
        __syncthreads();
#pragma unroll
        for (int m = 0; m < 16; m++) { sre[t + m*256] = tr[m]; sim[t + m*256] = ti[m]; }
        __syncthreads();
    }

    // ---- <Z_q> = sum p_i * (1 - 2*bit_{11-q}(i)) ----
    float z[12];
#pragma unroll
    for (int q = 0; q < 12; q++) z[q] = 0.f;
#pragma unroll
    for (int m = 0; m < 16; m++) {
        int i = t + m * 256;
        float p = sre[i]*sre[i] + sim[i]*sim[i];
#pragma unroll
        for (int q = 0; q < 12; q++) z[q] += ((i >> (11 - q)) & 1) ? -p : p;
    }
#pragma unroll
    for (int q = 0; q < 12; q++)
#pragma unroll
        for (int o = 16; o; o >>= 1) z[q] += __shfl_xor_sync(~0u, z[q], o);
    if (!l)
#pragma unroll
        for (int q = 0; q < 12; q++) zr[w][q] = z[q];
    __syncthreads();
    if (t < 12) {
        float acc = 0.f;
#pragma unroll
        for (int k = 0; k < 8; k++) acc += zr[k][t];
        out[(long long)blockIdx.x * 12 + t] = acc;
    }
}

extern "C" void kernel_launch(void* const* d_in, const int* in_sizes, int n_in,
                              void* d_out, int out_size) {
    const float* x      = (const float*)d_in[0];
    const float* params = (const float*)d_in[1];
    float* out = (float*)d_out;
    prep_gates<<<1, 64>>>(params);
    qc<<<8192, 256>>>(x, out);
}

// round 13
// speedup vs baseline: 1.4860x; 1.4860x over previous
#include <cuda_runtime.h>

#define NG 36

__device__ float d_gates[NG * 8];

// Fuse Rz*Ry*Rx per (layer,qubit) in double precision.
__global__ void prep_gates(const float* __restrict__ params) {
    int g = threadIdx.x;
    if (g >= NG) return;
    double tx = (double)params[3*g]   * 0.5;
    double ty = (double)params[3*g+1] * 0.5;
    double tz = (double)params[3*g+2] * 0.5;
    double cx = cos(tx), sx = sin(tx), cy = cos(ty), sy = sin(ty), cz = cos(tz), sz = sin(tz);
    double m00r =  cy*cx, m00i =  sy*sx;
    double m01r = -sy*cx, m01i = -cy*sx;
    double m10r =  sy*cx, m10i = -cy*sx;
    double m11r =  cy*cx, m11i = -sy*sx;
    float* o = d_gates + g * 8;
    o[0] = (float)(cz*m00r + sz*m00i); o[1] = (float)(cz*m00i - sz*m00r);
    o[2] = (float)(cz*m01r + sz*m01i); o[3] = (float)(cz*m01i - sz*m01r);
    o[4] = (float)(cz*m10r - sz*m10i); o[5] = (float)(cz*m10i + sz*m10r);
    o[6] = (float)(cz*m11r - sz*m11i); o[7] = (float)(cz*m11i + sz*m11r);
}

// Bank-conflict swizzle for smem exchanges.
#define SW(i) ((i) ^ (((i) >> 5) & 31))

// Apply 4 register-butterfly gates on local bits 0..3; bit b -> qubit (QB - b).
#define APPLY4(QB)                                                              \
    _Pragma("unroll")                                                           \
    for (int b = 0; b < 4; b++) {                                               \
        const float* u = gbase + ((QB) - b) * 8;                                \
        const float u00r=u[0],u00i=u[1],u01r=u[2],u01i=u[3];                    \
        const float u10r=u[4],u10i=u[5],u11r=u[6],u11i=u[7];                    \
        _Pragma("unroll")                                                       \
        for (int k0 = 0; k0 < 16; k0++) if (!(k0 & (1 << b))) {                 \
            const int k1 = k0 | (1 << b);                                       \
            float a0r=ar[k0], a0i=ai[k0], a1r=ar[k1], a1i=ai[k1];               \
            ar[k0] = u00r*a0r - u00i*a0i + u01r*a1r - u01i*a1i;                 \
            ai[k0] = u00r*a0i + u00i*a0r + u01r*a1i + u01i*a1r;                 \
            ar[k1] = u10r*a0r - u10i*a0i + u11r*a1r - u11i*a1i;                 \
            ai[k1] = u10r*a0i + u10i*a0r + u11r*a1i + u11i*a1r;                 \
        }                                                                       \
    }

// One batch element per CTA; 256 threads x 16 register-resident amplitudes.
// Wire q <-> bit (11-q) of the flattened index.
__global__ void __launch_bounds__(256, 3) qc(const float* __restrict__ x,
                                             float* __restrict__ out) {
    __shared__ float sre[4096], sim[4096];
    __shared__ float sg[NG * 8];
    __shared__ float red[8];
    __shared__ float zr[8][12];

    const int t = threadIdx.x, w = t >> 5, l = t & 31;

    for (int e = t; e < NG * 8; e += 256) sg[e] = d_gates[e];

    // ---- load (phase-A ownership: i = (t<<4)|k, 16 contiguous floats) ----
    float ar[16], ai[16];
    const float4* xv = (const float4*)(x + (long long)blockIdx.x * 4096 + t * 16);
    float s = 0.f;
#pragma unroll
    for (int m = 0; m < 4; m++) {
        float4 f = xv[m];
        ar[4*m] = f.x; ar[4*m+1] = f.y; ar[4*m+2] = f.z; ar[4*m+3] = f.w;
        s += f.x*f.x + f.y*f.y + f.z*f.z + f.w*f.w;
    }
#pragma unroll
    for (int o = 16; o; o >>= 1) s += __shfl_xor_sync(~0u, s, o);
    if (!l) red[w] = s;
    __syncthreads();   // also covers sg copy
    s = red[0] + red[1] + red[2] + red[3] + red[4] + red[5] + red[6] + red[7];
    const float rn = rsqrtf(s);
#pragma unroll
    for (int k = 0; k < 16; k++) { ar[k] *= rn; ai[k] = 0.f; }

    // ---- circuit: 3 phases of 4 local gates + 3 smem exchanges per layer ----
    for (int L = 0; L < 3; L++) {
        const float* gbase = &sg[L * 96];

        // Phase A: local bits 0..3 = qubits 11..8
        APPLY4(11)

        // exchange A -> B  (B: i = ((t>>4)<<8) | (k<<4) | (t&15), local bits 4..7)
#pragma unroll
        for (int k = 0; k < 16; k++) {
            int i = (t << 4) | k;
            sre[SW(i)] = ar[k]; sim[SW(i)] = ai[k];
        }
        __syncthreads();
#pragma unroll
        for (int k = 0; k < 16; k++) {
            int i = ((t >> 4) << 8) | (k << 4) | (t & 15);
            ar[k] = sre[SW(i)]; ai[k] = sim[SW(i)];
        }
        __syncthreads();

        // Phase B: local bits 4..7 = qubits 7..4
        APPLY4(7)

        // exchange B -> C  (C: i = (k<<8) | t, local bits 8..11)
#pragma unroll
        for (int k = 0; k < 16; k++) {
            int i = ((t >> 4) << 8) | (k << 4) | (t & 15);
            sre[SW(i)] = ar[k]; sim[SW(i)] = ai[k];
        }
        __syncthreads();
#pragma unroll
        for (int k = 0; k < 16; k++) {
            int i = (k << 8) | t;
            ar[k] = sre[SW(i)]; ai[k] = sim[SW(i)];
        }
        __syncthreads();

        // Phase C: local bits 8..11 = qubits 3..0
        APPLY4(3)

        // exchange C -> A with CNOT-ring permutation folded into the gather
#pragma unroll
        for (int k = 0; k < 16; k++) {
            int i = (k << 8) | t;
            sre[SW(i)] = ar[k]; sim[SW(i)] = ai[k];
        }
        __syncthreads();
#pragma unroll
        for (int k = 0; k < 16; k++) {
            int i = (t << 4) | k;
            int lo  = (i ^ (i >> 1)) & 0x3FF;            // b_j = c_j ^ c_{j+1}, j=0..9
            int b10 = ((i >> 10) ^ (i >> 11) ^ i) & 1;   // c10 ^ c11 ^ c0
            int b11 = ((i >> 11) ^ i) & 1;               // c11 ^ c0
            int src = lo | (b10 << 10) | (b11 << 11);
            ar[k] = sre[SW(src)]; ai[k] = sim[SW(src)];
        }
        __syncthreads();
    }

    // ---- readout: registers hold A-layout (i = (t<<4)|k) final state ----
    float ptot = 0.f, zb0 = 0.f, zb1 = 0.f, zb2 = 0.f, zb3 = 0.f;
#pragma unroll
    for (int k = 0; k < 16; k++) {
        float p = ar[k]*ar[k] + ai[k]*ai[k];
        ptot += p;
        zb0 += (k & 1) ? -p : p;
        zb1 += (k & 2) ? -p : p;
        zb2 += (k & 4) ? -p : p;
        zb3 += (k & 8) ? -p : p;
    }
    float z[12];
#pragma unroll
    for (int q = 0; q < 8; q++)            // bit (11-q) of i = bit (7-q) of t
        z[q] = ((t >> (7 - q)) & 1) ? -ptot : ptot;
    z[8] = zb3; z[9] = zb2; z[10] = zb1; z[11] = zb0;

#pragma unroll
    for (int q = 0; q < 12; q++)
#pragma unroll
        for (int o = 16; o; o >>= 1) z[q] += __shfl_xor_sync(~0u, z[q], o);
    if (!l)
#pragma unroll
        for (int q = 0; q < 12; q++) zr[w][q] = z[q];
    __syncthreads();
    if (t < 12) {
        float acc = 0.f;
#pragma unroll
        for (int k = 0; k < 8; k++) acc += zr[k][t];
        out[(long long)blockIdx.x * 12 + t] = acc;
    }
}

extern "C" void kernel_launch(void* const* d_in, const int* in_sizes, int n_in,
                              void* d_out, int out_size) {
    const float* x      = (const float*)d_in[0];
    const float* params = (const float*)d_in[1];
    float* out = (float*)d_out;
    prep_gates<<<1, 64>>>(params);
    qc<<<8192, 256>>>(x, out);
}

// round 14
// speedup vs baseline: 1.6885x; 1.1363x over previous
#include <cuda_runtime.h>

typedef unsigned long long u64;
#define NG 36

__device__ float d_gates[NG * 8];

// Fuse Rz*Ry*Rx per (layer,qubit) in double precision.
__global__ void prep_gates(const float* __restrict__ params) {
    int g = threadIdx.x;
    if (g >= NG) return;
    double tx = (double)params[3*g]   * 0.5;
    double ty = (double)params[3*g+1] * 0.5;
    double tz = (double)params[3*g+2] * 0.5;
    double cx = cos(tx), sx = sin(tx), cy = cos(ty), sy = sin(ty), cz = cos(tz), sz = sin(tz);
    double m00r =  cy*cx, m00i =  sy*sx;
    double m01r = -sy*cx, m01i = -cy*sx;
    double m10r =  sy*cx, m10i = -cy*sx;
    double m11r =  cy*cx, m11i = -sy*sx;
    float* o = d_gates + g * 8;
    o[0] = (float)(cz*m00r + sz*m00i); o[1] = (float)(cz*m00i - sz*m00r);
    o[2] = (float)(cz*m01r + sz*m01i); o[3] = (float)(cz*m01i - sz*m01r);
    o[4] = (float)(cz*m10r - sz*m10i); o[5] = (float)(cz*m10i + sz*m10r);
    o[6] = (float)(cz*m11r - sz*m11i); o[7] = (float)(cz*m11i + sz*m11r);
}

// ---- f32x2 helpers ----
static __device__ __forceinline__ u64 f2(float a, float b) {
    u64 r; asm("mov.b64 %0,{%1,%2};" : "=l"(r) : "r"(__float_as_uint(a)), "r"(__float_as_uint(b))); return r;
}
static __device__ __forceinline__ u64 bc(float v) { return f2(v, v); }
static __device__ __forceinline__ float f2lo(u64 p) { return __uint_as_float((unsigned)p); }
static __device__ __forceinline__ float f2hi(u64 p) { return __uint_as_float((unsigned)(p >> 32)); }
static __device__ __forceinline__ u64 f2swap(u64 p) {
    u64 r; asm("{.reg .b32 a,b; mov.b64 {a,b},%1; mov.b64 %0,{b,a};}" : "=l"(r) : "l"(p)); return r;
}
static __device__ __forceinline__ u64 fma2(u64 a, u64 b, u64 c) {
    u64 d; asm("fma.rn.f32x2 %0,%1,%2,%3;" : "=l"(d) : "l"(a), "l"(b), "l"(c)); return d;
}
static __device__ __forceinline__ u64 mul2(u64 a, u64 b) {
    u64 d; asm("mul.rn.f32x2 %0,%1,%2;" : "=l"(d) : "l"(a), "l"(b)); return d;
}

// Bank-conflict swizzle for smem exchanges.
#define SW(i) ((i) ^ (((i) >> 5) & 31))

// 4 gates on the 4 local bits. Pack lane = local bit0 (qubit QB, in-pack via
// lane swap); pack-index bits 0..2 = local bits 1..3 (qubits QB-1..QB-3).
#define APPLY4P(QB) do {                                                        \
    { const float* u = gbase + (QB) * 8;                                        \
      u64 Au=f2(u[0],u[6]), Bu=f2(u[2],u[4]);                                   \
      u64 Cu=f2(-u[1],-u[7]), Du=f2(-u[3],-u[5]);                               \
      u64 Eu=f2(u[1],u[7]), Fu=f2(u[3],u[5]);                                   \
      _Pragma("unroll")                                                         \
      for (int j = 0; j < 8; j++) {                                             \
          u64 sr=f2swap(pr[j]), si=f2swap(pi[j]);                               \
          u64 nr=mul2(Au,pr[j]); nr=fma2(Bu,sr,nr);                             \
          nr=fma2(Cu,pi[j],nr);  nr=fma2(Du,si,nr);                             \
          u64 ni=mul2(Au,pi[j]); ni=fma2(Bu,si,ni);                             \
          ni=fma2(Eu,pr[j],ni);  ni=fma2(Fu,sr,ni);                             \
          pr[j]=nr; pi[j]=ni;                                                   \
      } }                                                                       \
    _Pragma("unroll")                                                           \
    for (int b = 1; b < 4; b++) {                                               \
        const float* u = gbase + ((QB) - b) * 8;                                \
        u64 r00=bc(u[0]), i00=bc(u[1]), n00=bc(-u[1]);                          \
        u64 r01=bc(u[2]), i01=bc(u[3]), n01=bc(-u[3]);                          \
        u64 r10=bc(u[4]), i10=bc(u[5]), n10=bc(-u[5]);                          \
        u64 r11=bc(u[6]), i11=bc(u[7]), n11=bc(-u[7]);                          \
        const int m = 1 << (b - 1);                                             \
        _Pragma("unroll")                                                       \
        for (int j = 0; j < 8; j++) if (!(j & m)) {                             \
            const int j1 = j | m;                                               \
            u64 a0r=pr[j], a0i=pi[j], a1r=pr[j1], a1i=pi[j1], t0;               \
            t0=mul2(r00,a0r); t0=fma2(n00,a0i,t0); t0=fma2(r01,a1r,t0); pr[j] =fma2(n01,a1i,t0); \
            t0=mul2(r00,a0i); t0=fma2(i00,a0r,t0); t0=fma2(r01,a1i,t0); pi[j] =fma2(i01,a1r,t0); \
            t0=mul2(r10,a0r); t0=fma2(n10,a0i,t0); t0=fma2(r11,a1r,t0); pr[j1]=fma2(n11,a1i,t0); \
            t0=mul2(r10,a0i); t0=fma2(i10,a0r,t0); t0=fma2(r11,a1i,t0); pi[j1]=fma2(i11,a1r,t0); \
        }                                                                       \
    }                                                                           \
} while (0)

// One batch element per CTA; 256 threads x 8 f32x2 packs (16 amps).
// Wire q <-> bit (11-q) of the flattened index.
__global__ void __launch_bounds__(256, 2) qc(const float* __restrict__ x,
                                             float* __restrict__ out) {
    __shared__ float sre[4096], sim[4096];
    __shared__ float sg[NG * 8];
    __shared__ float red[8];
    __shared__ float zr[8][12];

    const int t = threadIdx.x, w = t >> 5, l = t & 31;

    for (int e = t; e < NG * 8; e += 256) sg[e] = d_gates[e];

    // ---- load (phase-A ownership: i = (t<<4)|k, 16 contiguous floats) ----
    u64 pr[8], pi[8];
    const float4* xv = (const float4*)(x + (long long)blockIdx.x * 4096 + t * 16);
    float s = 0.f;
#pragma unroll
    for (int m = 0; m < 4; m++) {
        float4 f = xv[m];
        pr[2*m]   = f2(f.x, f.y);
        pr[2*m+1] = f2(f.z, f.w);
        s += f.x*f.x + f.y*f.y + f.z*f.z + f.w*f.w;
    }
#pragma unroll
    for (int o = 16; o; o >>= 1) s += __shfl_xor_sync(~0u, s, o);
    if (!l) red[w] = s;
    __syncthreads();   // also covers sg copy
    s = red[0] + red[1] + red[2] + red[3] + red[4] + red[5] + red[6] + red[7];
    const u64 rn = bc(rsqrtf(s));
#pragma unroll
    for (int j = 0; j < 8; j++) { pr[j] = mul2(pr[j], rn); pi[j] = 0ull; }

    // ---- circuit: 3 phases of 4 local gates + 3 smem exchanges per layer ----
    for (int L = 0; L < 3; L++) {
        const float* gbase = &sg[L * 96];

        // Phase A: local bits 0..3 = qubits 11..8
        APPLY4P(11);

        // exchange A -> B  (B: i = ((t>>4)<<8)|(k<<4)|(t&15), local bits 4..7)
#pragma unroll
        for (int j = 0; j < 8; j++) {
            int i0 = (t << 4) | (2*j);
            sre[SW(i0)]   = f2lo(pr[j]); sim[SW(i0)]   = f2lo(pi[j]);
            sre[SW(i0+1)] = f2hi(pr[j]); sim[SW(i0+1)] = f2hi(pi[j]);
        }
        __syncthreads();
#pragma unroll
        for (int j = 0; j < 8; j++) {
            int ia = ((t >> 4) << 8) | ((2*j) << 4) | (t & 15);
            int ib = ia | 16;
            pr[j] = f2(sre[SW(ia)], sre[SW(ib)]);
            pi[j] = f2(sim[SW(ia)], sim[SW(ib)]);
        }
        __syncthreads();

        // Phase B: local bits 4..7 = qubits 7..4
        APPLY4P(7);

        // exchange B -> C  (C: i = (k<<8)|t, local bits 8..11)
#pragma unroll
        for (int j = 0; j < 8; j++) {
            int ia = ((t >> 4) << 8) | ((2*j) << 4) | (t & 15);
            int ib = ia | 16;
            sre[SW(ia)] = f2lo(pr[j]); sim[SW(ia)] = f2lo(pi[j]);
            sre[SW(ib)] = f2hi(pr[j]); sim[SW(ib)] = f2hi(pi[j]);
        }
        __syncthreads();
#pragma unroll
        for (int j = 0; j < 8; j++) {
            int ia = ((2*j) << 8) | t;
            int ib = ia | 256;
            pr[j] = f2(sre[SW(ia)], sre[SW(ib)]);
            pi[j] = f2(sim[SW(ia)], sim[SW(ib)]);
        }
        __syncthreads();

        // Phase C: local bits 8..11 = qubits 3..0
        APPLY4P(3);

        // exchange C -> A with CNOT-ring permutation folded into the gather
#pragma unroll
        for (int j = 0; j < 8; j++) {
            int ia = ((2*j) << 8) | t;
            int ib = ia | 256;
            sre[SW(ia)] = f2lo(pr[j]); sim[SW(ia)] = f2lo(pi[j]);
            sre[SW(ib)] = f2hi(pr[j]); sim[SW(ib)] = f2hi(pi[j]);
        }
        __syncthreads();
#pragma unroll
        for (int j = 0; j < 8; j++) {
            float vr[2], vi[2];
#pragma unroll
            for (int h = 0; h < 2; h++) {
                int i = (t << 4) | (2*j + h);
                int lo  = (i ^ (i >> 1)) & 0x3FF;            // b_j = c_j ^ c_{j+1}, j=0..9
                int b10 = ((i >> 10) ^ (i >> 11) ^ i) & 1;   // c10 ^ c11 ^ c0
                int b11 = ((i >> 11) ^ i) & 1;               // c11 ^ c0
                int src = lo | (b10 << 10) | (b11 << 11);
                vr[h] = sre[SW(src)]; vi[h] = sim[SW(src)];
            }
            pr[j] = f2(vr[0], vr[1]); pi[j] = f2(vi[0], vi[1]);
        }
        __syncthreads();
    }

    // ---- readout: A layout, i = (t<<4)|(2j+h) ----
    float ptot = 0.f, zb0 = 0.f, zb1 = 0.f, zb2 = 0.f, zb3 = 0.f;
#pragma unroll
    for (int j = 0; j < 8; j++) {
        u64 p2 = fma2(pr[j], pr[j], mul2(pi[j], pi[j]));
        float plo = f2lo(p2), phi = f2hi(p2);
        float psum = plo + phi, pdif = plo - phi;
        ptot += psum;
        zb0  += pdif;                       // i bit0
        zb1  += (j & 1) ? -psum : psum;     // i bit1 = j bit0
        zb2  += (j & 2) ? -psum : psum;     // i bit2 = j bit1
        zb3  += (j & 4) ? -psum : psum;     // i bit3 = j bit2
    }
    float z[12];
#pragma unroll
    for (int q = 0; q < 8; q++)             // bit (11-q) of i = bit (7-q) of t
        z[q] = ((t >> (7 - q)) & 1) ? -ptot : ptot;
    z[8] = zb3; z[9] = zb2; z[10] = zb1; z[11] = zb0;

#pragma unroll
    for (int q = 0; q < 12; q++)
#pragma unroll
        for (int o = 16; o; o >>= 1) z[q] += __shfl_xor_sync(~0u, z[q], o);
    if (!l)
#pragma unroll
        for (int q = 0; q < 12; q++) zr[w][q] = z[q];
    __syncthreads();
    if (t < 12) {
        float acc = 0.f;
#pragma unroll
        for (int k = 0; k < 8; k++) acc += zr[k][t];
        out[(long long)blockIdx.x * 12 + t] = acc;
    }
}

extern "C" void kernel_launch(void* const* d_in, const int* in_sizes, int n_in,
                              void* d_out, int out_size) {
    const float* x      = (const float*)d_in[0];
    const float* params = (const float*)d_in[1];
    float* out = (float*)d_out;
    prep_gates<<<1, 64>>>(params);
    qc<<<8192, 256>>>(x, out);
}

// round 16
// speedup vs baseline: 1.7226x; 1.0202x over previous
#include <cuda_runtime.h>

typedef unsigned long long u64;
#define NG 36

__device__ float d_gates[NG * 8];

// Fuse Rz*Ry*Rx per (layer,qubit) in double precision.
__global__ void prep_gates(const float* __restrict__ params) {
    int g = threadIdx.x;
    if (g >= NG) return;
    double tx = (double)params[3*g]   * 0.5;
    double ty = (double)params[3*g+1] * 0.5;
    double tz = (double)params[3*g+2] * 0.5;
    double cx = cos(tx), sx = sin(tx), cy = cos(ty), sy = sin(ty), cz = cos(tz), sz = sin(tz);
    double m00r =  cy*cx, m00i =  sy*sx;
    double m01r = -sy*cx, m01i = -cy*sx;
    double m10r =  sy*cx, m10i = -cy*sx;
    double m11r =  cy*cx, m11i = -sy*sx;
    float* o = d_gates + g * 8;
    o[0] = (float)(cz*m00r + sz*m00i); o[1] = (float)(cz*m00i - sz*m00r);
    o[2] = (float)(cz*m01r + sz*m01i); o[3] = (float)(cz*m01i - sz*m01r);
    o[4] = (float)(cz*m10r - sz*m10i); o[5] = (float)(cz*m10i + sz*m10r);
    o[6] = (float)(cz*m11r - sz*m11i); o[7] = (float)(cz*m11i + sz*m11r);
}

// ---- f32x2 helpers ----
static __device__ __forceinline__ u64 f2(float a, float b) {
    u64 r; asm("mov.b64 %0,{%1,%2};" : "=l"(r) : "r"(__float_as_uint(a)), "r"(__float_as_uint(b))); return r;
}
static __device__ __forceinline__ u64 bc(float v) { return f2(v, v); }
static __device__ __forceinline__ float f2lo(u64 p) { return __uint_as_float((unsigned)p); }
static __device__ __forceinline__ float f2hi(u64 p) { return __uint_as_float((unsigned)(p >> 32)); }
static __device__ __forceinline__ u64 f2swap(u64 p) {
    u64 r; asm("{.reg .b32 a,b; mov.b64 {a,b},%1; mov.b64 %0,{b,a};}" : "=l"(r) : "l"(p)); return r;
}
static __device__ __forceinline__ u64 fma2(u64 a, u64 b, u64 c) {
    u64 d; asm("fma.rn.f32x2 %0,%1,%2,%3;" : "=l"(d) : "l"(a), "l"(b), "l"(c)); return d;
}
static __device__ __forceinline__ u64 mul2(u64 a, u64 b) {
    u64 d; asm("mul.rn.f32x2 %0,%1,%2;" : "=l"(d) : "l"(a), "l"(b)); return d;
}

// Bank-conflict swizzle for smem exchanges.
#define SW(i) ((i) ^ (((i) >> 5) & 31))

// 4 gates on the 4 local bits. Pack lane = local bit0 (qubit QB, in-pack via
// lane swap); pack-index bits 0..2 = local bits 1..3 (qubits QB-1..QB-3).
#define APPLY4P(QB) do {                                                        \
    { const float* u = gbase + (QB) * 8;                                        \
      u64 Au=f2(u[0],u[6]), Bu=f2(u[2],u[4]);                                   \
      u64 Cu=f2(-u[1],-u[7]), Du=f2(-u[3],-u[5]);                               \
      u64 Eu=f2(u[1],u[7]), Fu=f2(u[3],u[5]);                                   \
      _Pragma("unroll")                                                         \
      for (int j = 0; j < 8; j++) {                                             \
          u64 sr=f2swap(pr[j]), si=f2swap(pi[j]);                               \
          u64 nr=mul2(Au,pr[j]); nr=fma2(Bu,sr,nr);                             \
          nr=fma2(Cu,pi[j],nr);  nr=fma2(Du,si,nr);                             \
          u64 ni=mul2(Au,pi[j]); ni=fma2(Bu,si,ni);                             \
          ni=fma2(Eu,pr[j],ni);  ni=fma2(Fu,sr,ni);                             \
          pr[j]=nr; pi[j]=ni;                                                   \
      } }                                                                       \
    _Pragma("unroll")                                                           \
    for (int b = 1; b < 4; b++) {                                               \
        const float* u = gbase + ((QB) - b) * 8;                                \
        u64 r00=bc(u[0]), i00=bc(u[1]), n00=bc(-u[1]);                          \
        u64 r01=bc(u[2]), i01=bc(u[3]), n01=bc(-u[3]);                          \
        u64 r10=bc(u[4]), i10=bc(u[5]), n10=bc(-u[5]);                          \
        u64 r11=bc(u[6]), i11=bc(u[7]), n11=bc(-u[7]);                          \
        const int m = 1 << (b - 1);                                             \
        _Pragma("unroll")                                                       \
        for (int j = 0; j < 8; j++) if (!(j & m)) {                             \
            const int j1 = j | m;                                               \
            u64 a0r=pr[j], a0i=pi[j], a1r=pr[j1], a1i=pi[j1], t0;               \
            t0=mul2(r00,a0r); t0=fma2(n00,a0i,t0); t0=fma2(r01,a1r,t0); pr[j] =fma2(n01,a1i,t0); \
            t0=mul2(r00,a0i); t0=fma2(i00,a0r,t0); t0=fma2(r01,a1i,t0); pi[j] =fma2(i01,a1r,t0); \
            t0=mul2(r10,a0r); t0=fma2(n10,a0i,t0); t0=fma2(r11,a1r,t0); pr[j1]=fma2(n11,a1i,t0); \
            t0=mul2(r10,a0i); t0=fma2(i10,a0r,t0); t0=fma2(r11,a1i,t0); pi[j1]=fma2(i11,a1r,t0); \
        }                                                                       \
    }                                                                           \
} while (0)

// One batch element per CTA; 256 threads x 8 f32x2 packs (16 amps).
// Wire q <-> bit (11-q) of the flattened index.
__global__ void __launch_bounds__(256, 3) qc(const float* __restrict__ x,
                                             float* __restrict__ out) {
    __shared__ float sre[4096], sim[4096];
    __shared__ float sg[NG * 8];
    __shared__ float red[8];
    __shared__ float zr[8][12];

    const int t = threadIdx.x, w = t >> 5, l = t & 31;

    for (int e = t; e < NG * 8; e += 256) sg[e] = d_gates[e];

    // ---- load (phase-A ownership: i = (t<<4)|k, 16 contiguous floats) ----
    u64 pr[8], pi[8];
    const float4* xv = (const float4*)(x + (long long)blockIdx.x * 4096 + t * 16);
    float s = 0.f;
#pragma unroll
    for (int m = 0; m < 4; m++) {
        float4 f = xv[m];
        pr[2*m]   = f2(f.x, f.y);
        pr[2*m+1] = f2(f.z, f.w);
        s += f.x*f.x + f.y*f.y + f.z*f.z + f.w*f.w;
    }
#pragma unroll
    for (int o = 16; o; o >>= 1) s += __shfl_xor_sync(~0u, s, o);
    if (!l) red[w] = s;
    __syncthreads();   // also covers sg copy
    s = red[0] + red[1] + red[2] + red[3] + red[4] + red[5] + red[6] + red[7];
    const u64 rn = bc(rsqrtf(s));
#pragma unroll
    for (int j = 0; j < 8; j++) { pr[j] = mul2(pr[j], rn); pi[j] = 0ull; }

    // ---- circuit: 3 phases of 4 local gates + 3 smem exchanges per layer ----
    for (int L = 0; L < 3; L++) {
        const float* gbase = &sg[L * 96];

        // Phase A: local bits 0..3 = qubits 11..8
        APPLY4P(11);

        // exchange A -> B  (B: i = ((t>>4)<<8)|(k<<4)|(t&15), local bits 4..7)
#pragma unroll
        for (int j = 0; j < 8; j++) {
            int i0 = (t << 4) | (2*j);
            sre[SW(i0)]   = f2lo(pr[j]); sim[SW(i0)]   = f2lo(pi[j]);
            sre[SW(i0+1)] = f2hi(pr[j]); sim[SW(i0+1)] = f2hi(pi[j]);
        }
        __syncthreads();
#pragma unroll
        for (int j = 0; j < 8; j++) {
            int ia = ((t >> 4) << 8) | ((2*j) << 4) | (t & 15);
            int ib = ia | 16;
            pr[j] = f2(sre[SW(ia)], sre[SW(ib)]);
            pi[j] = f2(sim[SW(ia)], sim[SW(ib)]);
        }
        __syncthreads();

        // Phase B: local bits 4..7 = qubits 7..4
        APPLY4P(7);

        // exchange B -> C  (C: i = (k<<8)|t, local bits 8..11)
#pragma unroll
        for (int j = 0; j < 8; j++) {
            int ia = ((t >> 4) << 8) | ((2*j) << 4) | (t & 15);
            int ib = ia | 16;
            sre[SW(ia)] = f2lo(pr[j]); sim[SW(ia)] = f2lo(pi[j]);
            sre[SW(ib)] = f2hi(pr[j]); sim[SW(ib)] = f2hi(pi[j]);
        }
        __syncthreads();
#pragma unroll
        for (int j = 0; j < 8; j++) {
            int ia = ((2*j) << 8) | t;
            int ib = ia | 256;
            pr[j] = f2(sre[SW(ia)], sre[SW(ib)]);
            pi[j] = f2(sim[SW(ia)], sim[SW(ib)]);
        }
        __syncthreads();

        // Phase C: local bits 8..11 = qubits 3..0
        APPLY4P(3);

        // exchange C -> A with CNOT-ring permutation folded into the gather
#pragma unroll
        for (int j = 0; j < 8; j++) {
            int ia = ((2*j) << 8) | t;
            int ib = ia | 256;
            sre[SW(ia)] = f2lo(pr[j]); sim[SW(ia)] = f2lo(pi[j]);
            sre[SW(ib)] = f2hi(pr[j]); sim[SW(ib)] = f2hi(pi[j]);
        }
        __syncthreads();
#pragma unroll
        for (int j = 0; j < 8; j++) {
            float vr[2], vi[2];
#pragma unroll
            for (int h = 0; h < 2; h++) {
                int i = (t << 4) | (2*j + h);
                int lo  = (i ^ (i >> 1)) & 0x3FF;            // b_j = c_j ^ c_{j+1}, j=0..9
                int b10 = ((i >> 10) ^ (i >> 11) ^ i) & 1;   // c10 ^ c11 ^ c0
                int b11 = ((i >> 11) ^ i) & 1;               // c11 ^ c0
                int src = lo | (b10 << 10) | (b11 << 11);
                vr[h] = sre[SW(src)]; vi[h] = sim[SW(src)];
            }
            pr[j] = f2(vr[0], vr[1]); pi[j] = f2(vi[0], vi[1]);
        }
        __syncthreads();
    }

    // ---- readout: A layout, i = (t<<4)|(2j+h) ----
    float ptot = 0.f, zb0 = 0.f, zb1 = 0.f, zb2 = 0.f, zb3 = 0.f;
#pragma unroll
    for (int j = 0; j < 8; j++) {
        u64 p2 = fma2(pr[j], pr[j], mul2(pi[j], pi[j]));
        float plo = f2lo(p2), phi = f2hi(p2);
        float psum = plo + phi, pdif = plo - phi;
        ptot += psum;
        zb0  += pdif;                       // i bit0
        zb1  += (j & 1) ? -psum : psum;     // i bit1 = j bit0
        zb2  += (j & 2) ? -psum : psum;     // i bit2 = j bit1
        zb3  += (j & 4) ? -psum : psum;     // i bit3 = j bit2
    }
    float z[12];
#pragma unroll
    for (int q = 0; q < 8; q++)             // bit (11-q) of i = bit (7-q) of t
        z[q] = ((t >> (7 - q)) & 1) ? -ptot : ptot;
    z[8] = zb3; z[9] = zb2; z[10] = zb1; z[11] = zb0;

#pragma unroll
    for (int q = 0; q < 12; q++)
#pragma unroll
        for (int o = 16; o; o >>= 1) z[q] += __shfl_xor_sync(~0u, z[q], o);
    if (!l)
#pragma unroll
        for (int q = 0; q < 12; q++) zr[w][q] = z[q];
    __syncthreads();
    if (t < 12) {
        float acc = 0.f;
#pragma unroll
        for (int k = 0; k < 8; k++) acc += zr[k][t];
        out[(long long)blockIdx.x * 12 + t] = acc;
    }
}

extern "C" void kernel_launch(void* const* d_in, const int* in_sizes, int n_in,
                              void* d_out, int out_size) {
    const float* x      = (const float*)d_in[0];
    const float* params = (const float*)d_in[1];
    float* out = (float*)d_out;
    prep_gates<<<1, 64>>>(params);
    qc<<<8192, 256>>>(x, out);
}